// round 12
// baseline (speedup 1.0000x reference)
#include <cuda_runtime.h>
#include <cuda_fp16.h>
#include <cstdint>
#include <cmath>

// Problem constants
#define BB   8
#define TT   4096
#define DD   256
#define MTOT (BB*TT)        // 32768
#define KTOT 512            // 2 taps x 256
#define NSEG 64
#define SEGL (TT/NSEG)      // 64

// GEMM tiling: fp16, BM=128, BN=256 (whole gate), BK=64 halves (128B rows)
#define BM 128
#define BN 256
#define BK 64
#define NKB (KTOT/BK)       // 8
#define STAGES 2
#define A_BYTES (BM*128)            // 16384
#define B_BYTES (BN*128)            // 32768
#define STAGE_BYTES (A_BYTES+B_BYTES)   // 49152
#define DYN_SMEM (STAGES*STAGE_BYTES)   // 98304 -> 2 CTAs/SM

// ---------------- scratch (device globals) ----------------
__device__ float  g_z[(size_t)MTOT*DD];
__device__ float  g_f[(size_t)MTOT*DD];
__device__ float  g_o[(size_t)MTOT*DD];
__device__ __half g_xh[(size_t)MTOT*DD];      // x in fp16 (RN)
__device__ __half g_wh[3*DD*KTOT];            // Wt[g][n][k], k-major, fp16
__device__ float  g_segA[BB*NSEG*DD];
__device__ float  g_segB[BB*NSEG*DD];
__device__ float  g_carry[BB*NSEG*DD];

// ---------------- helpers ----------------
__device__ __forceinline__ uint32_t smem_u32(const void* p) {
    uint32_t a;
    asm("{ .reg .u64 t; cvta.to.shared.u64 t, %1; cvt.u32.u64 %0, t; }" : "=r"(a) : "l"(p));
    return a;
}
__device__ __forceinline__ void cp_async16(uint32_t dst, const void* src, uint32_t src_bytes) {
    asm volatile("cp.async.cg.shared.global [%0], [%1], 16, %2;"
                 :: "r"(dst), "l"(src), "r"(src_bytes) : "memory");
}
__device__ __forceinline__ void cp_commit() {
    asm volatile("cp.async.commit_group;" ::: "memory");
}
template<int N> __device__ __forceinline__ void cp_wait() {
    asm volatile("cp.async.wait_group %0;" :: "n"(N) : "memory");
}
__device__ __forceinline__ void ldsm4(uint32_t& r0, uint32_t& r1, uint32_t& r2, uint32_t& r3,
                                      uint32_t addr) {
    asm volatile("ldmatrix.sync.aligned.m8n8.x4.shared.b16 {%0,%1,%2,%3}, [%4];"
                 : "=r"(r0), "=r"(r1), "=r"(r2), "=r"(r3) : "r"(addr));
}
__device__ __forceinline__ void mma_f16(float c[4], const uint32_t a[4], const uint32_t b[2]) {
    asm("mma.sync.aligned.m16n8k16.row.col.f32.f16.f16.f32 "
        "{%0,%1,%2,%3}, {%4,%5,%6,%7}, {%8,%9}, {%0,%1,%2,%3};"
        : "+f"(c[0]), "+f"(c[1]), "+f"(c[2]), "+f"(c[3])
        : "r"(a[0]), "r"(a[1]), "r"(a[2]), "r"(a[3]), "r"(b[0]), "r"(b[1]));
}

// ---------------- prep kernels ----------------
__global__ void cvt_x(const float* __restrict__ x) {
    size_t i = (size_t)blockIdx.x * 256 + threadIdx.x;   // over float4s
    float4 v = ((const float4*)x)[i];
    ((__half2*)g_xh)[i * 2]     = __floats2half2_rn(v.x, v.y);
    ((__half2*)g_xh)[i * 2 + 1] = __floats2half2_rn(v.z, v.w);
}

__global__ void trans_w(const float* __restrict__ Wz, const float* __restrict__ Wf,
                        const float* __restrict__ Wo) {
    __shared__ float t[32][33];
    int g = blockIdx.z, tap = blockIdx.y;
    const float* W = (g == 0) ? Wz : (g == 1) ? Wf : Wo;
    int d0 = (blockIdx.x & 7) * 32;
    int n0 = (blockIdx.x >> 3) * 32;
    #pragma unroll
    for (int r = 0; r < 4; r++) {
        int d = d0 + threadIdx.y + r * 8;
        t[threadIdx.y + r * 8][threadIdx.x] =
            W[(size_t)tap * 65536 + (size_t)d * 256 + n0 + threadIdx.x];
    }
    __syncthreads();
    #pragma unroll
    for (int r = 0; r < 4; r++) {
        int n = n0 + threadIdx.y + r * 8;
        g_wh[(size_t)g * (DD * KTOT) + (size_t)n * KTOT + tap * 256 + d0 + threadIdx.x] =
            __float2half_rn(t[threadIdx.x][threadIdx.y + r * 8]);
    }
}

// ---------------- fp16 mma.sync gate GEMM ----------------
// BM=128, BN=256, BK=64 halves, 2-stage cp.async, ldmatrix.
// 8 warps (2m x 4n), warp tile 64x64, m16n8k16.
__global__ __launch_bounds__(256)
void gates_gemm(const float* __restrict__ bz, const float* __restrict__ bfv,
                const float* __restrict__ bo) {
    extern __shared__ char dyn[];
    const uint32_t sbase = smem_u32(dyn);

    const int tid  = threadIdx.x;
    const int warp = tid >> 5, lane = tid & 31;
    const int gq = lane >> 2, q = lane & 3;
    const int wm0 = (warp >> 2) * 64;
    const int wn0 = (warp & 3) * 64;

    const int gate = blockIdx.x;           // n fast -> 3 gates share A tile in L2
    const int m0   = blockIdx.y * BM;

    const float* bias = (gate == 0) ? bz : (gate == 1) ? bfv : bo;
    float* dst        = (gate == 0) ? g_z : (gate == 1) ? g_f : g_o;
    const __half* Wb  = g_wh + (size_t)gate * (DD * KTOT);

    float acc[4][8][4];
    #pragma unroll
    for (int mt = 0; mt < 4; mt++)
        #pragma unroll
        for (int nt = 0; nt < 8; nt++)
            #pragma unroll
            for (int i = 0; i < 4; i++) acc[mt][nt][i] = 0.0f;

    // ---- producer: one BK=64-half stage (A 16KB + B 32KB) ----
    auto issue_stage = [&](int kb, int st) {
        const uint32_t abase = sbase + st * STAGE_BYTES;
        const uint32_t bbase = abase + A_BYTES;
        const int tap = kb >> 2;               // kb 0-3: tap0, 4-7: tap1
        const int d0  = (kb & 3) << 6;         // 64-half d-chunk within tap
        // A: 1024 chunks of 16B -> 4 per thread
        #pragma unroll
        for (int p = 0; p < 4; p++) {
            int idx = tid + p * 256;
            int row = idx >> 3;
            int k4  = idx & 7;
            uint32_t sw = (uint32_t)(row << 7) + (uint32_t)((k4 ^ (row & 7)) << 4);
            int m = m0 + row;
            const __half* srcA;
            uint32_t nb = 16;
            if (tap == 0) {
                srcA = g_xh + (size_t)(m - 1) * DD + d0 + (k4 << 3);
                if ((m & (TT - 1)) == 0) { nb = 0; srcA = g_xh; }
            } else {
                srcA = g_xh + (size_t)m * DD + d0 + (k4 << 3);
            }
            cp_async16(abase + sw, srcA, nb);
        }
        // B: 2048 chunks of 16B -> 8 per thread (k_total = kb*64)
        #pragma unroll
        for (int p = 0; p < 8; p++) {
            int idx = tid + p * 256;
            int row = idx >> 3;
            int k4  = idx & 7;
            uint32_t sw = (uint32_t)(row << 7) + (uint32_t)((k4 ^ (row & 7)) << 4);
            const __half* srcB = Wb + (size_t)row * KTOT + (kb << 6) + (k4 << 3);
            cp_async16(bbase + sw, srcB, 16);
        }
    };

    // ---- consumer: 4 k16-steps per stage, warp tile 64x64 ----
    const int mi1 = (lane >> 3) & 1;
    const int mi2 = lane >> 4;
    const int rr  = lane & 7;
    auto compute = [&](int st) {
        const uint32_t ab = sbase + st * STAGE_BYTES;
        const uint32_t bb = ab + A_BYTES;
        #pragma unroll
        for (int ks = 0; ks < 4; ks++) {
            uint32_t af[4][4], bf[8][2];
            #pragma unroll
            for (int mt = 0; mt < 4; mt++) {
                int row = wm0 + mt * 16 + mi1 * 8 + rr;
                int k4  = ks * 2 + mi2;
                uint32_t addr = ab + (row << 7) + ((k4 ^ (row & 7)) << 4);
                ldsm4(af[mt][0], af[mt][1], af[mt][2], af[mt][3], addr);
            }
            #pragma unroll
            for (int ntp = 0; ntp < 4; ntp++) {
                int row = wn0 + ntp * 16 + mi2 * 8 + rr;
                int k4  = ks * 2 + mi1;
                uint32_t addr = bb + (row << 7) + ((k4 ^ (row & 7)) << 4);
                uint32_t r0, r1, r2, r3;
                ldsm4(r0, r1, r2, r3, addr);
                bf[2*ntp][0] = r0;   bf[2*ntp][1] = r1;
                bf[2*ntp+1][0] = r2; bf[2*ntp+1][1] = r3;
            }
            #pragma unroll
            for (int mt = 0; mt < 4; mt++)
                #pragma unroll
                for (int nt = 0; nt < 8; nt++)
                    mma_f16(acc[mt][nt], af[mt], bf[nt]);
        }
    };

    // ---- pipeline: 8 k-chunks, 2 buffers ----
    issue_stage(0, 0); cp_commit();
    issue_stage(1, 1); cp_commit();

    for (int kb = 0; kb < NKB; kb++) {
        const int buf = kb & 1;
        cp_wait<1>();
        __syncthreads();
        compute(buf);
        __syncthreads();                         // all reads done before refill
        if (kb + 2 < NKB) issue_stage(kb + 2, buf);
        cp_commit();
    }

    // ---- epilogue: bias + activation, float2 stores ----
    #pragma unroll
    for (int mt = 0; mt < 4; mt++) {
        #pragma unroll
        for (int nt = 0; nt < 8; nt++) {
            #pragma unroll
            for (int h = 0; h < 2; h++) {
                int m = m0 + wm0 + mt * 16 + gq + h * 8;
                int n = wn0 + nt * 8 + q * 2;
                float v0 = acc[mt][nt][2*h]   + bias[n];
                float v1 = acc[mt][nt][2*h+1] + bias[n + 1];
                if (gate == 0) { v0 = tanhf(v0); v1 = tanhf(v1); }
                else { v0 = 1.0f / (1.0f + expf(-v0)); v1 = 1.0f / (1.0f + expf(-v1)); }
                *(float2*)(dst + (size_t)m * DD + n) = make_float2(v0, v1);
            }
        }
    }
}

// ---------------- segmented scan (proven fastest: scalar, 131072 threads) ----------------
__global__ void seg_reduce() {
    int tid = blockIdx.x * 256 + threadIdx.x;
    int d = tid & 255;
    int s = (tid >> 8) & (NSEG - 1);
    int b = tid >> 14;
    size_t base = ((size_t)b * TT + (size_t)s * SEGL) * DD + d;
    float A = 1.0f, Bv = 0.0f;
    #pragma unroll 4
    for (int i = 0; i < SEGL; i++) {
        float f = g_f[base + (size_t)i * DD];
        float z = g_z[base + (size_t)i * DD];
        A  = f * A;
        Bv = f * Bv + (1.0f - f) * z;
    }
    int sidx = (b * NSEG + s) * DD + d;
    g_segA[sidx] = A;
    g_segB[sidx] = Bv;
}

__global__ void seg_carry() {
    int tid = blockIdx.x * 256 + threadIdx.x;
    int d = tid & 255;
    int b = tid >> 8;
    float c = 0.0f;
    for (int s = 0; s < NSEG; s++) {
        int idx = (b * NSEG + s) * DD + d;
        g_carry[idx] = c;
        c = g_segA[idx] * c + g_segB[idx];
    }
}

__global__ void seg_apply(float* __restrict__ out) {
    int tid = blockIdx.x * 256 + threadIdx.x;
    int d = tid & 255;
    int s = (tid >> 8) & (NSEG - 1);
    int b = tid >> 14;
    size_t base = ((size_t)b * TT + (size_t)s * SEGL) * DD + d;
    float c = g_carry[(b * NSEG + s) * DD + d];
    #pragma unroll 4
    for (int i = 0; i < SEGL; i++) {
        size_t idx = base + (size_t)i * DD;
        float f = g_f[idx];
        float z = g_z[idx];
        float o = g_o[idx];
        c = f * c + (1.0f - f) * z;
        out[idx] = o * c;
    }
}

// ---------------- launch ----------------
extern "C" void kernel_launch(void* const* d_in, const int* in_sizes, int n_in,
                              void* d_out, int out_size) {
    const float* x   = (const float*)d_in[0];
    const float* Wz  = (const float*)d_in[1];
    const float* Wf  = (const float*)d_in[2];
    const float* Wo  = (const float*)d_in[3];
    const float* bz  = (const float*)d_in[4];
    const float* bfv = (const float*)d_in[5];
    const float* bo  = (const float*)d_in[6];
    float* out = (float*)d_out;

    cudaFuncSetAttribute(gates_gemm, cudaFuncAttributeMaxDynamicSharedMemorySize, DYN_SMEM);

    cvt_x<<<(MTOT * DD / 4) / 256, 256>>>(x);
    trans_w<<<dim3(64, 2, 3), dim3(32, 8)>>>(Wz, Wf, Wo);
    gates_gemm<<<dim3(3, MTOT / BM), 256, DYN_SMEM>>>(bz, bfv, bo);
    seg_reduce<<<(BB * NSEG * DD) / 256, 256>>>();
    seg_carry<<<(BB * DD) / 256, 256>>>();
    seg_apply<<<(BB * NSEG * DD) / 256, 256>>>(out);
}

// round 13
// speedup vs baseline: 1.2004x; 1.2004x over previous
#include <cuda_runtime.h>
#include <cuda_fp16.h>
#include <cstdint>
#include <cmath>

// Problem constants
#define BB   8
#define TT   4096
#define DD   256
#define MTOT (BB*TT)        // 32768
#define KTOT 512            // 2 taps x 256
#define NSEG 128
#define SEGL (TT/NSEG)      // 32

// GEMM tiling: fp16, BK=64 halves (128B rows)  [R11 proven geometry]
#define BM 128
#define BN 128
#define BK 64
#define NKB (KTOT/BK)       // 8
#define STAGES 3
#define A_BYTES (BM*128)            // 16384
#define B_BYTES (BN*128)            // 16384
#define STAGE_BYTES (A_BYTES+B_BYTES)
#define DYN_SMEM (STAGES*STAGE_BYTES)   // 98304 -> 2 CTAs/SM

// ---------------- scratch (device globals) ----------------
__device__ float  g_z[(size_t)MTOT*DD];
__device__ float  g_f[(size_t)MTOT*DD];
__device__ float  g_o[(size_t)MTOT*DD];
__device__ __half g_xh[(size_t)MTOT*DD];      // x in fp16 (RN)
__device__ __half g_wh[3*DD*KTOT];            // Wt[g][n][k], k-major, fp16
__device__ float  g_segA[BB*NSEG*DD];
__device__ float  g_segB[BB*NSEG*DD];
__device__ float  g_carry[BB*NSEG*DD];

// ---------------- helpers ----------------
__device__ __forceinline__ uint32_t smem_u32(const void* p) {
    uint32_t a;
    asm("{ .reg .u64 t; cvta.to.shared.u64 t, %1; cvt.u32.u64 %0, t; }" : "=r"(a) : "l"(p));
    return a;
}
__device__ __forceinline__ void cp_async16(uint32_t dst, const void* src, uint32_t src_bytes) {
    asm volatile("cp.async.cg.shared.global [%0], [%1], 16, %2;"
                 :: "r"(dst), "l"(src), "r"(src_bytes) : "memory");
}
__device__ __forceinline__ void cp_commit() {
    asm volatile("cp.async.commit_group;" ::: "memory");
}
template<int N> __device__ __forceinline__ void cp_wait() {
    asm volatile("cp.async.wait_group %0;" :: "n"(N) : "memory");
}
__device__ __forceinline__ void ldsm4(uint32_t& r0, uint32_t& r1, uint32_t& r2, uint32_t& r3,
                                      uint32_t addr) {
    asm volatile("ldmatrix.sync.aligned.m8n8.x4.shared.b16 {%0,%1,%2,%3}, [%4];"
                 : "=r"(r0), "=r"(r1), "=r"(r2), "=r"(r3) : "r"(addr));
}
__device__ __forceinline__ void mma_f16(float c[4], const uint32_t a[4], const uint32_t b[2]) {
    asm("mma.sync.aligned.m16n8k16.row.col.f32.f16.f16.f32 "
        "{%0,%1,%2,%3}, {%4,%5,%6,%7}, {%8,%9}, {%0,%1,%2,%3};"
        : "+f"(c[0]), "+f"(c[1]), "+f"(c[2]), "+f"(c[3])
        : "r"(a[0]), "r"(a[1]), "r"(a[2]), "r"(a[3]), "r"(b[0]), "r"(b[1]));
}

// ---------------- prep kernels ----------------
__global__ void cvt_x(const float* __restrict__ x) {
    size_t i = (size_t)blockIdx.x * 256 + threadIdx.x;   // over float4s
    float4 v = ((const float4*)x)[i];
    ((__half2*)g_xh)[i * 2]     = __floats2half2_rn(v.x, v.y);
    ((__half2*)g_xh)[i * 2 + 1] = __floats2half2_rn(v.z, v.w);
}

__global__ void trans_w(const float* __restrict__ Wz, const float* __restrict__ Wf,
                        const float* __restrict__ Wo) {
    __shared__ float t[32][33];
    int g = blockIdx.z, tap = blockIdx.y;
    const float* W = (g == 0) ? Wz : (g == 1) ? Wf : Wo;
    int d0 = (blockIdx.x & 7) * 32;
    int n0 = (blockIdx.x >> 3) * 32;
    #pragma unroll
    for (int r = 0; r < 4; r++) {
        int d = d0 + threadIdx.y + r * 8;
        t[threadIdx.y + r * 8][threadIdx.x] =
            W[(size_t)tap * 65536 + (size_t)d * 256 + n0 + threadIdx.x];
    }
    __syncthreads();
    #pragma unroll
    for (int r = 0; r < 4; r++) {
        int n = n0 + threadIdx.y + r * 8;
        g_wh[(size_t)g * (DD * KTOT) + (size_t)n * KTOT + tap * 256 + d0 + threadIdx.x] =
            __float2half_rn(t[threadIdx.x][threadIdx.y + r * 8]);
    }
}

// ---------------- fp16 mma.sync gate GEMM (R11 geometry, reordered pipeline) ----------------
// BM=128, BN=128, BK=64 halves, 3-stage cp.async, ldmatrix.
// 8 warps (2m x 4n), warp tile 64x32, m16n8k16, 2 CTAs/SM.
__global__ __launch_bounds__(256, 2)
void gates_gemm(const float* __restrict__ bz, const float* __restrict__ bfv,
                const float* __restrict__ bo) {
    extern __shared__ char dyn[];
    const uint32_t sbase = smem_u32(dyn);

    const int tid  = threadIdx.x;
    const int warp = tid >> 5, lane = tid & 31;
    const int gq = lane >> 2, q = lane & 3;
    const int wm0 = (warp & 1) * 64;
    const int wn0 = (warp >> 1) * 32;

    const int n0   = blockIdx.x * BN;      // n fast -> A reuse in L2 within a wave
    const int m0   = blockIdx.y * BM;
    const int gate = n0 >> 8;
    const int n0g  = n0 & 255;

    const float* bias = (gate == 0) ? bz : (gate == 1) ? bfv : bo;
    float* dst        = (gate == 0) ? g_z : (gate == 1) ? g_f : g_o;
    const __half* Wb  = g_wh + (size_t)gate * (DD * KTOT) + (size_t)n0g * KTOT;

    float acc[4][4][4];
    #pragma unroll
    for (int mt = 0; mt < 4; mt++)
        #pragma unroll
        for (int nt = 0; nt < 4; nt++)
            #pragma unroll
            for (int i = 0; i < 4; i++) acc[mt][nt][i] = 0.0f;

    // ---- producer: one BK=64-half stage (A 16KB + B 16KB) ----
    auto issue_stage = [&](int kb, int st) {
        const uint32_t abase = sbase + st * STAGE_BYTES;
        const uint32_t bbase = abase + A_BYTES;
        const int tap = kb >> 2;               // kb 0-3: tap0, 4-7: tap1
        const int d0  = (kb & 3) << 6;         // 64-half d-chunk within tap
        #pragma unroll
        for (int p = 0; p < 4; p++) {
            int idx = tid + p * 256;           // 1024 chunks of 16B (8 halves)
            int row = idx >> 3;
            int k4  = idx & 7;
            uint32_t sw = (uint32_t)(row << 7) + (uint32_t)((k4 ^ (row & 7)) << 4);
            // A
            int m = m0 + row;
            const __half* srcA;
            uint32_t nb = 16;
            if (tap == 0) {
                srcA = g_xh + (size_t)(m - 1) * DD + d0 + (k4 << 3);
                if ((m & (TT - 1)) == 0) { nb = 0; srcA = g_xh; }
            } else {
                srcA = g_xh + (size_t)m * DD + d0 + (k4 << 3);
            }
            cp_async16(abase + sw, srcA, nb);
            // B (n-major, k contiguous; k_total = kb*64)
            const __half* srcB = Wb + (size_t)row * KTOT + (kb << 6) + (k4 << 3);
            cp_async16(bbase + sw, srcB, 16);
        }
    };

    // ---- consumer: 4 k16-steps per stage ----
    const int mi1 = (lane >> 3) & 1;
    const int mi2 = lane >> 4;
    const int rr  = lane & 7;
    auto compute = [&](int st) {
        const uint32_t ab = sbase + st * STAGE_BYTES;
        const uint32_t bb = ab + A_BYTES;
        #pragma unroll
        for (int ks = 0; ks < 4; ks++) {
            uint32_t af[4][4], bf[4][2];
            #pragma unroll
            for (int mt = 0; mt < 4; mt++) {
                int row = wm0 + mt * 16 + mi1 * 8 + rr;
                int k4  = ks * 2 + mi2;
                uint32_t addr = ab + (row << 7) + ((k4 ^ (row & 7)) << 4);
                ldsm4(af[mt][0], af[mt][1], af[mt][2], af[mt][3], addr);
            }
            #pragma unroll
            for (int ntp = 0; ntp < 2; ntp++) {
                int row = wn0 + ntp * 16 + mi2 * 8 + rr;
                int k4  = ks * 2 + mi1;
                uint32_t addr = bb + (row << 7) + ((k4 ^ (row & 7)) << 4);
                uint32_t r0, r1, r2, r3;
                ldsm4(r0, r1, r2, r3, addr);
                bf[2*ntp][0] = r0;   bf[2*ntp][1] = r1;
                bf[2*ntp+1][0] = r2; bf[2*ntp+1][1] = r3;
            }
            #pragma unroll
            for (int mt = 0; mt < 4; mt++)
                #pragma unroll
                for (int nt = 0; nt < 4; nt++)
                    mma_f16(acc[mt][nt], af[mt], bf[nt]);
        }
    };

    // ---- pipeline: issue BEFORE compute so DMA overlaps the whole compute phase ----
    issue_stage(0, 0); cp_commit();
    issue_stage(1, 1); cp_commit();

    for (int kb = 0; kb < NKB; kb++) {
        cp_wait<1>();
        __syncthreads();                    // stage kb ready; stage kb-1 reads all done
        if (kb + 2 < NKB) issue_stage(kb + 2, (kb + 2) % STAGES);
        cp_commit();
        compute(kb % STAGES);
    }

    // ---- epilogue: bias + activation, float2 stores ----
    #pragma unroll
    for (int mt = 0; mt < 4; mt++) {
        #pragma unroll
        for (int nt = 0; nt < 4; nt++) {
            #pragma unroll
            for (int h = 0; h < 2; h++) {
                int m  = m0 + wm0 + mt * 16 + gq + h * 8;
                int n  = n0g + wn0 + nt * 8 + q * 2;
                float v0 = acc[mt][nt][2*h]   + bias[n];
                float v1 = acc[mt][nt][2*h+1] + bias[n + 1];
                if (gate == 0) { v0 = tanhf(v0); v1 = tanhf(v1); }
                else { v0 = 1.0f / (1.0f + expf(-v0)); v1 = 1.0f / (1.0f + expf(-v1)); }
                *(float2*)(dst + (size_t)m * DD + n) = make_float2(v0, v1);
            }
        }
    }
}

// ---------------- segmented scan: NSEG=128 (2x threads), scalar ----------------
__global__ void seg_reduce() {
    int tid = blockIdx.x * 256 + threadIdx.x;   // 262144 threads: (b, s, d)
    int d = tid & 255;
    int s = (tid >> 8) & (NSEG - 1);
    int b = tid >> 15;
    size_t base = ((size_t)b * TT + (size_t)s * SEGL) * DD + d;
    float A = 1.0f, Bv = 0.0f;
    #pragma unroll 8
    for (int i = 0; i < SEGL; i++) {
        float f = g_f[base + (size_t)i * DD];
        float z = g_z[base + (size_t)i * DD];
        A  = f * A;
        Bv = f * Bv + (1.0f - f) * z;
    }
    int sidx = (b * NSEG + s) * DD + d;
    g_segA[sidx] = A;
    g_segB[sidx] = Bv;
}

__global__ void seg_carry() {
    int tid = blockIdx.x * 256 + threadIdx.x;   // 2048 threads: (b, d)
    int d = tid & 255;
    int b = tid >> 8;
    float c = 0.0f;
    for (int s = 0; s < NSEG; s++) {
        int idx = (b * NSEG + s) * DD + d;
        g_carry[idx] = c;
        c = g_segA[idx] * c + g_segB[idx];
    }
}

__global__ void seg_apply(float* __restrict__ out) {
    int tid = blockIdx.x * 256 + threadIdx.x;   // 262144 threads
    int d = tid & 255;
    int s = (tid >> 8) & (NSEG - 1);
    int b = tid >> 15;
    size_t base = ((size_t)b * TT + (size_t)s * SEGL) * DD + d;
    float c = g_carry[(b * NSEG + s) * DD + d];
    #pragma unroll 8
    for (int i = 0; i < SEGL; i++) {
        size_t idx = base + (size_t)i * DD;
        float f = g_f[idx];
        float z = g_z[idx];
        float o = g_o[idx];
        c = f * c + (1.0f - f) * z;
        out[idx] = o * c;
    }
}

// ---------------- launch ----------------
extern "C" void kernel_launch(void* const* d_in, const int* in_sizes, int n_in,
                              void* d_out, int out_size) {
    const float* x   = (const float*)d_in[0];
    const float* Wz  = (const float*)d_in[1];
    const float* Wf  = (const float*)d_in[2];
    const float* Wo  = (const float*)d_in[3];
    const float* bz  = (const float*)d_in[4];
    const float* bfv = (const float*)d_in[5];
    const float* bo  = (const float*)d_in[6];
    float* out = (float*)d_out;

    cudaFuncSetAttribute(gates_gemm, cudaFuncAttributeMaxDynamicSharedMemorySize, DYN_SMEM);

    cvt_x<<<(MTOT * DD / 4) / 256, 256>>>(x);
    trans_w<<<dim3(64, 2, 3), dim3(32, 8)>>>(Wz, Wf, Wo);
    gates_gemm<<<dim3(768 / BN, MTOT / BM), 256, DYN_SMEM>>>(bz, bfv, bo);
    seg_reduce<<<(BB * NSEG * DD) / 256, 256>>>();
    seg_carry<<<(BB * DD) / 256, 256>>>();
    seg_apply<<<(BB * NSEG * DD) / 256, 256>>>(out);
}

// round 14
// speedup vs baseline: 1.2829x; 1.0687x over previous
#include <cuda_runtime.h>
#include <cuda_fp16.h>
#include <cstdint>
#include <cmath>

// Problem constants
#define BB   8
#define TT   4096
#define DD   256
#define MTOT (BB*TT)        // 32768
#define KTOT 512            // 2 taps x 256
#define NSEG 128
#define SEGL (TT/NSEG)      // 32

// GEMM tiling: fp16, BK=64 halves (128B rows)  [R11 proven geometry]
#define BM 128
#define BN 128
#define BK 64
#define NKB (KTOT/BK)       // 8
#define STAGES 3
#define A_BYTES (BM*128)            // 16384
#define B_BYTES (BN*128)            // 16384
#define STAGE_BYTES (A_BYTES+B_BYTES)
#define DYN_SMEM (STAGES*STAGE_BYTES)   // 98304

// ---------------- scratch (device globals) ----------------
__device__ __half g_zh[(size_t)MTOT*DD];      // gates stored fp16
__device__ __half g_fh[(size_t)MTOT*DD];
__device__ __half g_oh[(size_t)MTOT*DD];
__device__ __half g_xh[(size_t)MTOT*DD];      // x in fp16 (RN)
__device__ __half g_wh[3*DD*KTOT];            // Wt[g][n][k], k-major, fp16
__device__ float  g_segA[BB*NSEG*DD];
__device__ float  g_segB[BB*NSEG*DD];
__device__ float  g_carry[BB*NSEG*DD];

// ---------------- helpers ----------------
__device__ __forceinline__ uint32_t smem_u32(const void* p) {
    uint32_t a;
    asm("{ .reg .u64 t; cvta.to.shared.u64 t, %1; cvt.u32.u64 %0, t; }" : "=r"(a) : "l"(p));
    return a;
}
__device__ __forceinline__ void cp_async16(uint32_t dst, const void* src, uint32_t src_bytes) {
    asm volatile("cp.async.cg.shared.global [%0], [%1], 16, %2;"
                 :: "r"(dst), "l"(src), "r"(src_bytes) : "memory");
}
__device__ __forceinline__ void cp_commit() {
    asm volatile("cp.async.commit_group;" ::: "memory");
}
template<int N> __device__ __forceinline__ void cp_wait() {
    asm volatile("cp.async.wait_group %0;" :: "n"(N) : "memory");
}
__device__ __forceinline__ void ldsm4(uint32_t& r0, uint32_t& r1, uint32_t& r2, uint32_t& r3,
                                      uint32_t addr) {
    asm volatile("ldmatrix.sync.aligned.m8n8.x4.shared.b16 {%0,%1,%2,%3}, [%4];"
                 : "=r"(r0), "=r"(r1), "=r"(r2), "=r"(r3) : "r"(addr));
}
__device__ __forceinline__ void mma_f16(float c[4], const uint32_t a[4], const uint32_t b[2]) {
    asm("mma.sync.aligned.m16n8k16.row.col.f32.f16.f16.f32 "
        "{%0,%1,%2,%3}, {%4,%5,%6,%7}, {%8,%9}, {%0,%1,%2,%3};"
        : "+f"(c[0]), "+f"(c[1]), "+f"(c[2]), "+f"(c[3])
        : "r"(a[0]), "r"(a[1]), "r"(a[2]), "r"(a[3]), "r"(b[0]), "r"(b[1]));
}

// ---------------- prep kernels ----------------
__global__ void cvt_x(const float* __restrict__ x) {
    size_t i = (size_t)blockIdx.x * 256 + threadIdx.x;   // over float4s
    float4 v = ((const float4*)x)[i];
    ((__half2*)g_xh)[i * 2]     = __floats2half2_rn(v.x, v.y);
    ((__half2*)g_xh)[i * 2 + 1] = __floats2half2_rn(v.z, v.w);
}

__global__ void trans_w(const float* __restrict__ Wz, const float* __restrict__ Wf,
                        const float* __restrict__ Wo) {
    __shared__ float t[32][33];
    int g = blockIdx.z, tap = blockIdx.y;
    const float* W = (g == 0) ? Wz : (g == 1) ? Wf : Wo;
    int d0 = (blockIdx.x & 7) * 32;
    int n0 = (blockIdx.x >> 3) * 32;
    #pragma unroll
    for (int r = 0; r < 4; r++) {
        int d = d0 + threadIdx.y + r * 8;
        t[threadIdx.y + r * 8][threadIdx.x] =
            W[(size_t)tap * 65536 + (size_t)d * 256 + n0 + threadIdx.x];
    }
    __syncthreads();
    #pragma unroll
    for (int r = 0; r < 4; r++) {
        int n = n0 + threadIdx.y + r * 8;
        g_wh[(size_t)g * (DD * KTOT) + (size_t)n * KTOT + tap * 256 + d0 + threadIdx.x] =
            __float2half_rn(t[threadIdx.x][threadIdx.y + r * 8]);
    }
}

// ---------------- fp16 mma.sync gate GEMM (R11 verbatim; fp16 gate stores) ----------------
// BM=128, BN=128, BK=64 halves, 3-stage cp.async, ldmatrix.
// 8 warps (2m x 4n), warp tile 64x32, m16n8k16.
__global__ __launch_bounds__(256)
void gates_gemm(const float* __restrict__ bz, const float* __restrict__ bfv,
                const float* __restrict__ bo) {
    extern __shared__ char dyn[];
    const uint32_t sbase = smem_u32(dyn);

    const int tid  = threadIdx.x;
    const int warp = tid >> 5, lane = tid & 31;
    const int gq = lane >> 2, q = lane & 3;
    const int wm0 = (warp & 1) * 64;
    const int wn0 = (warp >> 1) * 32;

    const int n0   = blockIdx.x * BN;      // n fast -> A reuse in L2 within a wave
    const int m0   = blockIdx.y * BM;
    const int gate = n0 >> 8;
    const int n0g  = n0 & 255;

    const float* bias = (gate == 0) ? bz : (gate == 1) ? bfv : bo;
    __half* dst       = (gate == 0) ? g_zh : (gate == 1) ? g_fh : g_oh;
    const __half* Wb  = g_wh + (size_t)gate * (DD * KTOT) + (size_t)n0g * KTOT;

    float acc[4][4][4];
    #pragma unroll
    for (int mt = 0; mt < 4; mt++)
        #pragma unroll
        for (int nt = 0; nt < 4; nt++)
            #pragma unroll
            for (int i = 0; i < 4; i++) acc[mt][nt][i] = 0.0f;

    // ---- producer: one BK=64-half stage (A 16KB + B 16KB) ----
    auto issue_stage = [&](int kb, int st) {
        const uint32_t abase = sbase + st * STAGE_BYTES;
        const uint32_t bbase = abase + A_BYTES;
        const int tap = kb >> 2;               // kb 0-3: tap0, 4-7: tap1
        const int d0  = (kb & 3) << 6;         // 64-half d-chunk within tap
        #pragma unroll
        for (int p = 0; p < 4; p++) {
            int idx = tid + p * 256;           // 1024 chunks of 16B (8 halves)
            int row = idx >> 3;
            int k4  = idx & 7;
            uint32_t sw = (uint32_t)(row << 7) + (uint32_t)((k4 ^ (row & 7)) << 4);
            // A
            int m = m0 + row;
            const __half* srcA;
            uint32_t nb = 16;
            if (tap == 0) {
                srcA = g_xh + (size_t)(m - 1) * DD + d0 + (k4 << 3);
                if ((m & (TT - 1)) == 0) { nb = 0; srcA = g_xh; }
            } else {
                srcA = g_xh + (size_t)m * DD + d0 + (k4 << 3);
            }
            cp_async16(abase + sw, srcA, nb);
            // B (n-major, k contiguous; k_total = kb*64)
            const __half* srcB = Wb + (size_t)row * KTOT + (kb << 6) + (k4 << 3);
            cp_async16(bbase + sw, srcB, 16);
        }
    };

    // ---- consumer: 4 k16-steps per stage ----
    const int mi1 = (lane >> 3) & 1;
    const int mi2 = lane >> 4;
    const int rr  = lane & 7;
    auto compute = [&](int st) {
        const uint32_t ab = sbase + st * STAGE_BYTES;
        const uint32_t bb = ab + A_BYTES;
        #pragma unroll
        for (int ks = 0; ks < 4; ks++) {
            uint32_t af[4][4], bf[4][2];
            #pragma unroll
            for (int mt = 0; mt < 4; mt++) {
                int row = wm0 + mt * 16 + mi1 * 8 + rr;
                int k4  = ks * 2 + mi2;
                uint32_t addr = ab + (row << 7) + ((k4 ^ (row & 7)) << 4);
                ldsm4(af[mt][0], af[mt][1], af[mt][2], af[mt][3], addr);
            }
            #pragma unroll
            for (int ntp = 0; ntp < 2; ntp++) {
                int row = wn0 + ntp * 16 + mi2 * 8 + rr;
                int k4  = ks * 2 + mi1;
                uint32_t addr = bb + (row << 7) + ((k4 ^ (row & 7)) << 4);
                uint32_t r0, r1, r2, r3;
                ldsm4(r0, r1, r2, r3, addr);
                bf[2*ntp][0] = r0;   bf[2*ntp][1] = r1;
                bf[2*ntp+1][0] = r2; bf[2*ntp+1][1] = r3;
            }
            #pragma unroll
            for (int mt = 0; mt < 4; mt++)
                #pragma unroll
                for (int nt = 0; nt < 4; nt++)
                    mma_f16(acc[mt][nt], af[mt], bf[nt]);
        }
    };

    // ---- pipeline (R11 order: wait, sync, compute, issue, commit) ----
    issue_stage(0, 0); cp_commit();
    issue_stage(1, 1); cp_commit();

    int st = 0;
    for (int kb = 0; kb < NKB; kb++) {
        cp_wait<1>();
        __syncthreads();
        compute(st);
        if (kb + 2 < NKB) issue_stage(kb + 2, (kb + 2) % STAGES);
        cp_commit();
        st = (st + 1 == STAGES) ? 0 : st + 1;
    }

    // ---- epilogue: bias + activation, fp16 gate stores (half2) ----
    #pragma unroll
    for (int mt = 0; mt < 4; mt++) {
        #pragma unroll
        for (int nt = 0; nt < 4; nt++) {
            #pragma unroll
            for (int h = 0; h < 2; h++) {
                int m  = m0 + wm0 + mt * 16 + gq + h * 8;
                int n  = n0g + wn0 + nt * 8 + q * 2;
                float v0 = acc[mt][nt][2*h]   + bias[n];
                float v1 = acc[mt][nt][2*h+1] + bias[n + 1];
                if (gate == 0) { v0 = tanhf(v0); v1 = tanhf(v1); }
                else { v0 = 1.0f / (1.0f + expf(-v0)); v1 = 1.0f / (1.0f + expf(-v1)); }
                *(__half2*)(dst + (size_t)m * DD + n) = __floats2half2_rn(v0, v1);
            }
        }
    }
}

// ---------------- segmented scan: fp16 gates, fp32 math, NSEG=128 ----------------
__global__ void seg_reduce() {
    int tid = blockIdx.x * 256 + threadIdx.x;   // 131072 threads: (b, s, d2)
    int d2 = tid & 127;
    int s  = (tid >> 7) & (NSEG - 1);
    int b  = tid >> 14;
    size_t base2 = (((size_t)b * TT + (size_t)s * SEGL) * DD) / 2 + d2;
    float Ax = 1.0f, Ay = 1.0f, Bx = 0.0f, By = 0.0f;
    #pragma unroll 8
    for (int i = 0; i < SEGL; i++) {
        float2 f = __half22float2(((const __half2*)g_fh)[base2 + (size_t)i * (DD/2)]);
        float2 z = __half22float2(((const __half2*)g_zh)[base2 + (size_t)i * (DD/2)]);
        Ax *= f.x; Ay *= f.y;
        Bx = f.x * Bx + (1.0f - f.x) * z.x;
        By = f.y * By + (1.0f - f.y) * z.y;
    }
    int sidx = (b * NSEG + s) * (DD/2) + d2;
    ((float2*)g_segA)[sidx] = make_float2(Ax, Ay);
    ((float2*)g_segB)[sidx] = make_float2(Bx, By);
}

__global__ void seg_carry() {
    int tid = blockIdx.x * 256 + threadIdx.x;   // 2048 threads: (b, d)
    int d = tid & 255;
    int b = tid >> 8;
    float c = 0.0f;
    for (int s = 0; s < NSEG; s++) {
        int idx = (b * NSEG + s) * DD + d;
        g_carry[idx] = c;
        c = g_segA[idx] * c + g_segB[idx];
    }
}

__global__ void seg_apply(float* __restrict__ out) {
    int tid = blockIdx.x * 256 + threadIdx.x;   // 131072 threads: (b, s, d2)
    int d2 = tid & 127;
    int s  = (tid >> 7) & (NSEG - 1);
    int b  = tid >> 14;
    size_t base2 = (((size_t)b * TT + (size_t)s * SEGL) * DD) / 2 + d2;
    float2 c = ((const float2*)g_carry)[(b * NSEG + s) * (DD/2) + d2];
    #pragma unroll 8
    for (int i = 0; i < SEGL; i++) {
        size_t idx = base2 + (size_t)i * (DD/2);
        float2 f = __half22float2(((const __half2*)g_fh)[idx]);
        float2 z = __half22float2(((const __half2*)g_zh)[idx]);
        float2 o = __half22float2(((const __half2*)g_oh)[idx]);
        c.x = f.x * c.x + (1.0f - f.x) * z.x;
        c.y = f.y * c.y + (1.0f - f.y) * z.y;
        ((float2*)out)[idx] = make_float2(o.x * c.x, o.y * c.y);
    }
}

// ---------------- launch ----------------
extern "C" void kernel_launch(void* const* d_in, const int* in_sizes, int n_in,
                              void* d_out, int out_size) {
    const float* x   = (const float*)d_in[0];
    const float* Wz  = (const float*)d_in[1];
    const float* Wf  = (const float*)d_in[2];
    const float* Wo  = (const float*)d_in[3];
    const float* bz  = (const float*)d_in[4];
    const float* bfv = (const float*)d_in[5];
    const float* bo  = (const float*)d_in[6];
    float* out = (float*)d_out;

    cudaFuncSetAttribute(gates_gemm, cudaFuncAttributeMaxDynamicSharedMemorySize, DYN_SMEM);

    cvt_x<<<(MTOT * DD / 4) / 256, 256>>>(x);
    trans_w<<<dim3(64, 2, 3), dim3(32, 8)>>>(Wz, Wf, Wo);
    gates_gemm<<<dim3(768 / BN, MTOT / BM), 256, DYN_SMEM>>>(bz, bfv, bo);
    seg_reduce<<<(BB * NSEG * DD / 2) / 256, 256>>>();
    seg_carry<<<(BB * DD) / 256, 256>>>();
    seg_apply<<<(BB * NSEG * DD / 2) / 256, 256>>>(out);
}

// round 15
// speedup vs baseline: 1.3287x; 1.0357x over previous
#include <cuda_runtime.h>
#include <cuda.h>
#include <cuda_fp16.h>
#include <cstdint>
#include <cmath>

// Problem constants
#define BB   8
#define TT   4096
#define DD   256
#define MTOT (BB*TT)        // 32768
#define KTOT 512            // 2 taps x 256
#define NSEG 128
#define SEGL (TT/NSEG)      // 32

// GEMM tiling: fp16, BK=64 halves (128B rows), R11 consumer geometry, TMA producer
#define BM 128
#define BN 128
#define BK 64
#define NKB (KTOT/BK)       // 8
#define STAGES 3
#define A_BYTES (BM*128)            // 16384
#define B_BYTES (BN*128)            // 16384
#define STAGE_BYTES (A_BYTES+B_BYTES)   // 32768
#define STAGE_TX STAGE_BYTES
#define DYN_SMEM (STAGES*STAGE_BYTES + 1024)   // 99328 (+align slack); 2 CTAs/SM

// ---------------- scratch (device globals) ----------------
__device__ __half g_zh[(size_t)MTOT*DD];      // gates stored fp16
__device__ __half g_fh[(size_t)MTOT*DD];
__device__ __half g_oh[(size_t)MTOT*DD];
__device__ __half g_xh[(size_t)MTOT*DD];      // x in fp16 (RN)
__device__ __half g_wh[3*DD*KTOT];            // Wt[g][n][k], k-major, fp16
__device__ float  g_segA[BB*NSEG*DD];
__device__ float  g_segB[BB*NSEG*DD];
__device__ float  g_carry[BB*NSEG*DD];

// ---------------- helpers ----------------
__device__ __forceinline__ uint32_t smem_u32(const void* p) {
    uint32_t a;
    asm("{ .reg .u64 t; cvta.to.shared.u64 t, %1; cvt.u32.u64 %0, t; }" : "=r"(a) : "l"(p));
    return a;
}
__device__ __forceinline__ void ldsm4(uint32_t& r0, uint32_t& r1, uint32_t& r2, uint32_t& r3,
                                      uint32_t addr) {
    asm volatile("ldmatrix.sync.aligned.m8n8.x4.shared.b16 {%0,%1,%2,%3}, [%4];"
                 : "=r"(r0), "=r"(r1), "=r"(r2), "=r"(r3) : "r"(addr));
}
__device__ __forceinline__ void mma_f16(float c[4], const uint32_t a[4], const uint32_t b[2]) {
    asm("mma.sync.aligned.m16n8k16.row.col.f32.f16.f16.f32 "
        "{%0,%1,%2,%3}, {%4,%5,%6,%7}, {%8,%9}, {%0,%1,%2,%3};"
        : "+f"(c[0]), "+f"(c[1]), "+f"(c[2]), "+f"(c[3])
        : "r"(a[0]), "r"(a[1]), "r"(a[2]), "r"(a[3]), "r"(b[0]), "r"(b[1]));
}
__device__ __forceinline__ void tma_load_2d(uint32_t dst, const void* map, int x, int y,
                                            uint32_t mbar) {
    asm volatile(
        "cp.async.bulk.tensor.2d.shared::cta.global.tile.mbarrier::complete_tx::bytes "
        "[%0], [%1, {%2, %3}], [%4];"
        :: "r"(dst), "l"(map), "r"(x), "r"(y), "r"(mbar) : "memory");
}
#define MBARRIER_INIT(addr, cnt) \
    asm volatile("mbarrier.init.shared.b64 [%0], %1;" :: "r"(addr), "r"(cnt) : "memory")
#define MBARRIER_EXPECT_TX(addr, bytes) \
    asm volatile("mbarrier.arrive.expect_tx.shared.b64 _, [%0], %1;" \
                 :: "r"(addr), "r"(bytes) : "memory")
#define FENCE_PROXY_ASYNC() \
    asm volatile("fence.proxy.async.shared::cta;" ::: "memory")
#define MBARRIER_WAIT_PARITY(addr, par) do {                                     \
    uint32_t _m = (addr), _p = (par), _done;                                     \
    asm volatile("{ .reg .pred p; mbarrier.try_wait.parity.acquire.cta.shared::cta.b64 p, [%1], %2;" \
                 " selp.b32 %0, 1, 0, p; }" : "=r"(_done) : "r"(_m), "r"(_p) : "memory"); \
    if (!_done) {                                                                \
        asm volatile("{ .reg .pred P1; WL%=:"                                    \
                     " mbarrier.try_wait.parity.acquire.cta.shared::cta.b64 P1, [%0], %1, 0x989680;" \
                     " @P1 bra.uni WD%=; bra.uni WL%=; WD%=: }"                  \
                     :: "r"(_m), "r"(_p) : "memory");                            \
    } } while (0)

// ---------------- prep kernels ----------------
__global__ void cvt_x(const float* __restrict__ x) {
    size_t i = (size_t)blockIdx.x * 256 + threadIdx.x;   // over float4s
    float4 v = ((const float4*)x)[i];
    ((__half2*)g_xh)[i * 2]     = __floats2half2_rn(v.x, v.y);
    ((__half2*)g_xh)[i * 2 + 1] = __floats2half2_rn(v.z, v.w);
}

__global__ void trans_w(const float* __restrict__ Wz, const float* __restrict__ Wf,
                        const float* __restrict__ Wo) {
    __shared__ float t[32][33];
    int g = blockIdx.z, tap = blockIdx.y;
    const float* W = (g == 0) ? Wz : (g == 1) ? Wf : Wo;
    int d0 = (blockIdx.x & 7) * 32;
    int n0 = (blockIdx.x >> 3) * 32;
    #pragma unroll
    for (int r = 0; r < 4; r++) {
        int d = d0 + threadIdx.y + r * 8;
        t[threadIdx.y + r * 8][threadIdx.x] =
            W[(size_t)tap * 65536 + (size_t)d * 256 + n0 + threadIdx.x];
    }
    __syncthreads();
    #pragma unroll
    for (int r = 0; r < 4; r++) {
        int n = n0 + threadIdx.y + r * 8;
        g_wh[(size_t)g * (DD * KTOT) + (size_t)n * KTOT + tap * 256 + d0 + threadIdx.x] =
            __float2half_rn(t[threadIdx.x][threadIdx.y + r * 8]);
    }
}

// ---------------- TMA-fed fp16 mma.sync gate GEMM ----------------
// BM=128, BN=128, BK=64 halves, 3-stage TMA+mbarrier pipeline.
// 8 warps (2m x 4n), warp tile 64x32, m16n8k16, 2 CTAs/SM.
// Stage kb: tap = kb>>2, d0 = (kb&3)*64. A tile rows = tokens (m0-1+tap) .. +127.
__global__ __launch_bounds__(256)
void gates_gemm(const __grid_constant__ CUtensorMap tma_a,
                const __grid_constant__ CUtensorMap tma_b,
                const float* __restrict__ bz, const float* __restrict__ bfv,
                const float* __restrict__ bo) {
    extern __shared__ char dyn[];
    __shared__ __align__(8) uint64_t s_mbar[STAGES];
    const uint32_t sbase = (smem_u32(dyn) + 1023u) & ~1023u;   // SW128 TMA needs 1024-align
    uint32_t mb[STAGES];
    #pragma unroll
    for (int i = 0; i < STAGES; i++) mb[i] = smem_u32(&s_mbar[i]);

    const int tid  = threadIdx.x;
    const int warp = tid >> 5, lane = tid & 31;
    const int gq = lane >> 2, q = lane & 3;
    const int wm0 = (warp & 1) * 64;
    const int wn0 = (warp >> 1) * 32;

    const int n0   = blockIdx.x * BN;      // n fast -> A tile reuse in L2 within a wave
    const int m0   = blockIdx.y * BM;
    const int gate = n0 >> 8;
    const int n0g  = n0 & 255;
    const bool first_blk = ((m0 & (TT - 1)) == 0);

    const float* bias = (gate == 0) ? bz : (gate == 1) ? bfv : bo;
    __half* dst       = (gate == 0) ? g_zh : (gate == 1) ? g_fh : g_oh;

    if (tid == 0) {
        #pragma unroll
        for (int i = 0; i < STAGES; i++) MBARRIER_INIT(mb[i], 1);
    }
    __syncthreads();

    float acc[4][4][4];
    #pragma unroll
    for (int mt = 0; mt < 4; mt++)
        #pragma unroll
        for (int nt = 0; nt < 4; nt++)
            #pragma unroll
            for (int i = 0; i < 4; i++) acc[mt][nt][i] = 0.0f;

    // ---- producer (tid 0): one stage = A box{64,128} + B box{64,128} ----
    auto issue = [&](int kb) {
        const int s = kb % STAGES;
        MBARRIER_EXPECT_TX(mb[s], STAGE_TX);
        // A: x = d-chunk, y = first token of tile (m0-1 for tap0, m0 for tap1).
        //    y = -1 rows zero-fill via TMA OOB.
        tma_load_2d(sbase + s * STAGE_BYTES, &tma_a,
                    (kb & 3) * 64, m0 - 1 + (kb >> 2), mb[s]);
        // B: x = k_total = kb*64, y = global n row = blockIdx.x*128
        tma_load_2d(sbase + s * STAGE_BYTES + A_BYTES, &tma_b,
                    kb * 64, blockIdx.x * 128, mb[s]);
    };

    // ---- consumer: 4 k16-steps per stage (R11 verbatim) ----
    const int mi1 = (lane >> 3) & 1;
    const int mi2 = lane >> 4;
    const int rr  = lane & 7;
    auto compute = [&](int s) {
        const uint32_t ab = sbase + s * STAGE_BYTES;
        const uint32_t bb = ab + A_BYTES;
        #pragma unroll
        for (int ks = 0; ks < 4; ks++) {
            uint32_t af[4][4], bf[4][2];
            #pragma unroll
            for (int mt = 0; mt < 4; mt++) {
                int row = wm0 + mt * 16 + mi1 * 8 + rr;
                int k4  = ks * 2 + mi2;
                uint32_t addr = ab + (row << 7) + ((k4 ^ (row & 7)) << 4);
                ldsm4(af[mt][0], af[mt][1], af[mt][2], af[mt][3], addr);
            }
            #pragma unroll
            for (int ntp = 0; ntp < 2; ntp++) {
                int row = wn0 + ntp * 16 + mi2 * 8 + rr;
                int k4  = ks * 2 + mi1;
                uint32_t addr = bb + (row << 7) + ((k4 ^ (row & 7)) << 4);
                uint32_t r0, r1, r2, r3;
                ldsm4(r0, r1, r2, r3, addr);
                bf[2*ntp][0] = r0;   bf[2*ntp][1] = r1;
                bf[2*ntp+1][0] = r2; bf[2*ntp+1][1] = r3;
            }
            #pragma unroll
            for (int mt = 0; mt < 4; mt++)
                #pragma unroll
                for (int nt = 0; nt < 4; nt++)
                    mma_f16(acc[mt][nt], af[mt], bf[nt]);
        }
    };

    // ---- pipeline: 8 stages, 3 buffers ----
    if (tid == 0) {
        FENCE_PROXY_ASYNC();          // order mbarrier init before first TMA
        issue(0); issue(1); issue(2);
    }

    for (int kb = 0; kb < NKB; kb++) {
        const int s = kb % STAGES;
        MBARRIER_WAIT_PARITY(mb[s], (kb / STAGES) & 1);
        if (first_blk && kb < 4) {
            // tap0 stage: smem A row 0 = token m0-1 (previous batch / OOB) -> zero it
            if (tid < 8) {
                const uint32_t a0 = sbase + s * STAGE_BYTES + (tid << 4);  // row0 swizzle=id
                asm volatile("st.shared.v4.b32 [%0], {%1,%1,%1,%1};"
                             :: "r"(a0), "r"(0) : "memory");
            }
            __syncthreads();
        }
        compute(s);
        __syncthreads();              // all warps done reading slot s before reissue
        if (tid == 0 && kb + STAGES < NKB) {
            FENCE_PROXY_ASYNC();      // order generic fixup writes before async reuse
            issue(kb + STAGES);
        }
    }

    // ---- epilogue: bias + activation, fp16 gate stores ----
    #pragma unroll
    for (int mt = 0; mt < 4; mt++) {
        #pragma unroll
        for (int nt = 0; nt < 4; nt++) {
            #pragma unroll
            for (int h = 0; h < 2; h++) {
                int m  = m0 + wm0 + mt * 16 + gq + h * 8;
                int n  = n0g + wn0 + nt * 8 + q * 2;
                float v0 = acc[mt][nt][2*h]   + bias[n];
                float v1 = acc[mt][nt][2*h+1] + bias[n + 1];
                if (gate == 0) { v0 = tanhf(v0); v1 = tanhf(v1); }
                else { v0 = 1.0f / (1.0f + expf(-v0)); v1 = 1.0f / (1.0f + expf(-v1)); }
                *(__half2*)(dst + (size_t)m * DD + n) = __floats2half2_rn(v0, v1);
            }
        }
    }
}

// ---------------- segmented scan: fp16 gates, fp32 math, NSEG=128 (R14 proven) ----------------
__global__ void seg_reduce() {
    int tid = blockIdx.x * 256 + threadIdx.x;   // 131072 threads: (b, s, d2)
    int d2 = tid & 127;
    int s  = (tid >> 7) & (NSEG - 1);
    int b  = tid >> 14;
    size_t base2 = (((size_t)b * TT + (size_t)s * SEGL) * DD) / 2 + d2;
    float Ax = 1.0f, Ay = 1.0f, Bx = 0.0f, By = 0.0f;
    #pragma unroll 8
    for (int i = 0; i < SEGL; i++) {
        float2 f = __half22float2(((const __half2*)g_fh)[base2 + (size_t)i * (DD/2)]);
        float2 z = __half22float2(((const __half2*)g_zh)[base2 + (size_t)i * (DD/2)]);
        Ax *= f.x; Ay *= f.y;
        Bx = f.x * Bx + (1.0f - f.x) * z.x;
        By = f.y * By + (1.0f - f.y) * z.y;
    }
    int sidx = (b * NSEG + s) * (DD/2) + d2;
    ((float2*)g_segA)[sidx] = make_float2(Ax, Ay);
    ((float2*)g_segB)[sidx] = make_float2(Bx, By);
}

__global__ void seg_carry() {
    int tid = blockIdx.x * 256 + threadIdx.x;   // 2048 threads: (b, d)
    int d = tid & 255;
    int b = tid >> 8;
    float c = 0.0f;
    for (int s = 0; s < NSEG; s++) {
        int idx = (b * NSEG + s) * DD + d;
        g_carry[idx] = c;
        c = g_segA[idx] * c + g_segB[idx];
    }
}

__global__ void seg_apply(float* __restrict__ out) {
    int tid = blockIdx.x * 256 + threadIdx.x;   // 131072 threads: (b, s, d2)
    int d2 = tid & 127;
    int s  = (tid >> 7) & (NSEG - 1);
    int b  = tid >> 14;
    size_t base2 = (((size_t)b * TT + (size_t)s * SEGL) * DD) / 2 + d2;
    float2 c = ((const float2*)g_carry)[(b * NSEG + s) * (DD/2) + d2];
    #pragma unroll 8
    for (int i = 0; i < SEGL; i++) {
        size_t idx = base2 + (size_t)i * (DD/2);
        float2 f = __half22float2(((const __half2*)g_fh)[idx]);
        float2 z = __half22float2(((const __half2*)g_zh)[idx]);
        float2 o = __half22float2(((const __half2*)g_oh)[idx]);
        c.x = f.x * c.x + (1.0f - f.x) * z.x;
        c.y = f.y * c.y + (1.0f - f.y) * z.y;
        ((float2*)out)[idx] = make_float2(o.x * c.x, o.y * c.y);
    }
}

// ---------------- launch ----------------
typedef CUresult (*EncodeFn)(CUtensorMap*, CUtensorMapDataType, cuuint32_t, void*,
                             const cuuint64_t*, const cuuint64_t*, const cuuint32_t*,
                             const cuuint32_t*, CUtensorMapInterleave, CUtensorMapSwizzle,
                             CUtensorMapL2promotion, CUtensorMapFloatOOBfill);

extern "C" void kernel_launch(void* const* d_in, const int* in_sizes, int n_in,
                              void* d_out, int out_size) {
    const float* x   = (const float*)d_in[0];
    const float* Wz  = (const float*)d_in[1];
    const float* Wf  = (const float*)d_in[2];
    const float* Wo  = (const float*)d_in[3];
    const float* bz  = (const float*)d_in[4];
    const float* bfv = (const float*)d_in[5];
    const float* bo  = (const float*)d_in[6];
    float* out = (float*)d_out;

    // encode tensormaps (host-side, capture-safe, deterministic every call)
    void* encode_fn = nullptr;
    cudaDriverEntryPointQueryResult qr;
    cudaGetDriverEntryPointByVersion("cuTensorMapEncodeTiled", &encode_fn, 12000,
                                     cudaEnableDefault, &qr);
    void *xa = nullptr, *wa = nullptr;
    cudaGetSymbolAddress(&xa, g_xh);
    cudaGetSymbolAddress(&wa, g_wh);

    CUtensorMap tmap_a, tmap_b;
    {
        cuuint64_t dims[2]    = { 256, 32768 };          // {d cols, token rows}
        cuuint64_t strides[1] = { 256 * 2 };             // 512B row
        cuuint32_t box[2]     = { 64, 128 };             // 128B x 128 rows (SW128 ok)
        cuuint32_t es[2]      = { 1, 1 };
        ((EncodeFn)encode_fn)(&tmap_a, CU_TENSOR_MAP_DATA_TYPE_FLOAT16, 2, xa,
                              dims, strides, box, es,
                              CU_TENSOR_MAP_INTERLEAVE_NONE, CU_TENSOR_MAP_SWIZZLE_128B,
                              CU_TENSOR_MAP_L2_PROMOTION_L2_128B,
                              CU_TENSOR_MAP_FLOAT_OOB_FILL_NONE);
    }
    {
        cuuint64_t dims[2]    = { 512, 768 };            // {k cols, 3*256 n rows}
        cuuint64_t strides[1] = { 512 * 2 };             // 1024B row
        cuuint32_t box[2]     = { 64, 128 };
        cuuint32_t es[2]      = { 1, 1 };
        ((EncodeFn)encode_fn)(&tmap_b, CU_TENSOR_MAP_DATA_TYPE_FLOAT16, 2, wa,
                              dims, strides, box, es,
                              CU_TENSOR_MAP_INTERLEAVE_NONE, CU_TENSOR_MAP_SWIZZLE_128B,
                              CU_TENSOR_MAP_L2_PROMOTION_L2_128B,
                              CU_TENSOR_MAP_FLOAT_OOB_FILL_NONE);
    }

    cudaFuncSetAttribute(gates_gemm, cudaFuncAttributeMaxDynamicSharedMemorySize, DYN_SMEM);

    cvt_x<<<(MTOT * DD / 4) / 256, 256>>>(x);
    trans_w<<<dim3(64, 2, 3), dim3(32, 8)>>>(Wz, Wf, Wo);
    gates_gemm<<<dim3(768 / BN, MTOT / BM), 256, DYN_SMEM>>>(tmap_a, tmap_b, bz, bfv, bo);
    seg_reduce<<<(BB * NSEG * DD / 2) / 256, 256>>>();
    seg_carry<<<(BB * DD) / 256, 256>>>();
    seg_apply<<<(BB * NSEG * DD / 2) / 256, 256>>>(out);
}